// round 11
// baseline (speedup 1.0000x reference)
#include <cuda_runtime.h>
#include <cstdint>

#define NN 100000
#define DD 128
#define EPS 1e-5f
#define EMAX 3200000
#define NBLK_SCAN 98   // ceil(NN/1024)

// ---------------- device scratch (no allocations allowed) ----------------
__device__ float g_h[(size_t)NN * DD];     // h = x@W (raw); then h2; then h3
__device__ float g_acc[(size_t)NN * DD];   // t
__device__ float g_u[(size_t)NN * 256];    // FFN hidden
__device__ float g_dinv[NN];
__device__ int   g_cnt[NN];
__device__ int   g_off[NN];
__device__ int   g_cursor[NN];
__device__ int   g_bsum[NBLK_SCAN];
__device__ int   g_srcs[EMAX];
__device__ float g_sum[3 * DD];
__device__ float g_sq[3 * DD];

// ---------------- small helpers ----------------
__device__ __forceinline__ float f2tf32(float x) {
    uint32_t u;
    asm("cvt.rna.tf32.f32 %0, %1;" : "=r"(u) : "f"(x));
    return __uint_as_float(u);
}

__device__ __forceinline__ void mma_tf32(float4& d, const uint4& a, const uint2& b) {
    asm volatile(
        "mma.sync.aligned.m16n8k8.row.col.f32.tf32.tf32.f32 "
        "{%0,%1,%2,%3}, {%4,%5,%6,%7}, {%8,%9}, {%0,%1,%2,%3};"
        : "+f"(d.x), "+f"(d.y), "+f"(d.z), "+f"(d.w)
        : "r"(a.x), "r"(a.y), "r"(a.z), "r"(a.w), "r"(b.x), "r"(b.y));
}

// compute BN affine coeffs for column c of stats set `set`
__device__ __forceinline__ void bn_coeff(int set, const float* __restrict__ gamma,
                                         const float* __restrict__ beta,
                                         int c, float& sc, float& sh) {
    float m = g_sum[set * DD + c] * (1.0f / NN);
    float v = g_sq[set * DD + c] * (1.0f / NN) - m * m;
    float rs = rsqrtf(v + EPS);
    sc = gamma[c] * rs;
    sh = beta[c] - sc * m;
}

// ---------------- init / degree / CSR build ----------------
__global__ void init_kernel() {
    int i = blockIdx.x * blockDim.x + threadIdx.x;
    if (i < NN) g_cnt[i] = 0;
    if (i < 3 * DD) { g_sum[i] = 0.f; g_sq[i] = 0.f; }
}

__global__ void count_kernel(const int* __restrict__ ei, int E) {
    int e = blockIdx.x * blockDim.x + threadIdx.x;
    if (e < E) atomicAdd(&g_cnt[ei[E + e]], 1);
}

__global__ void scan1_kernel() {
    __shared__ int sh[256];
    int blk = blockIdx.x, tid = threadIdx.x;
    int i0 = blk * 1024 + tid * 4;
    int c0 = (i0 + 0 < NN) ? g_cnt[i0 + 0] : 0;
    int c1 = (i0 + 1 < NN) ? g_cnt[i0 + 1] : 0;
    int c2 = (i0 + 2 < NN) ? g_cnt[i0 + 2] : 0;
    int c3 = (i0 + 3 < NN) ? g_cnt[i0 + 3] : 0;
    int s = c0 + c1 + c2 + c3;
    sh[tid] = s;
    __syncthreads();
    for (int off = 1; off < 256; off <<= 1) {
        int v = (tid >= off) ? sh[tid - off] : 0;
        __syncthreads();
        sh[tid] += v;
        __syncthreads();
    }
    int excl = sh[tid] - s;
    if (tid == 255) g_bsum[blk] = sh[255];
    if (i0 + 0 < NN) g_off[i0 + 0] = excl;
    if (i0 + 1 < NN) g_off[i0 + 1] = excl + c0;
    if (i0 + 2 < NN) g_off[i0 + 2] = excl + c0 + c1;
    if (i0 + 3 < NN) g_off[i0 + 3] = excl + c0 + c1 + c2;
}

// folds the block-sum exclusive scan into each thread
__global__ void scan3_kernel() {
    int i = blockIdx.x * blockDim.x + threadIdx.x;
    if (i < NN) {
        int q = i >> 10;
        int base = 0;
        for (int j = 0; j < q; j++) base += g_bsum[j];
        int v = g_off[i] + base;
        g_off[i] = v;
        g_cursor[i] = v;
        g_dinv[i] = rsqrtf(1.0f + (float)g_cnt[i]);   // self loop included
    }
}

__global__ void fill_kernel(const int* __restrict__ ei, int E) {
    int e = blockIdx.x * blockDim.x + threadIdx.x;
    if (e < E) {
        int d = ei[E + e];
        int p = atomicAdd(&g_cursor[d], 1);
        g_srcs[p] = ei[e];
    }
}

// ---------------- tf32 tensor-core GEMM ----------------
// Tile 128x128, BK=32, 256 threads = 8 warps (2x4), warp tile 64x32.
// MODE 0: g_h = x @ W   (raw, no dinv — keeps gemm0 independent of CSR build)
// MODE 1: g_u = relu(affine1(g_h) @ W1 + b1)                  (K=128, NLD=256)
// MODE 2: g_h = g_u @ W2 + b2 + affine1(g_h); stats set 2     (K=256, NLD=128)
template<int MODE, int K, int NLD>
__global__ __launch_bounds__(256) void gemm_tc(const float* __restrict__ Ax,
                                               const float* __restrict__ B,
                                               const float* __restrict__ bias,
                                               const float* __restrict__ gamma,
                                               const float* __restrict__ beta)
{
    __shared__ __align__(16) float As[4096];  // [slice(4)][am(8)][lane(32)][reg(4)]
    __shared__ __align__(16) float Bs[4096];  // [slice(4)][bn(16)][lane(32)][reg(2)]
    __shared__ float scS[DD], shS[DD];
    __shared__ float stS[2 * DD];
    const float* A = (MODE == 0) ? Ax : (MODE == 1 ? (const float*)g_h : (const float*)g_u);

    int tid = threadIdx.x;
    int row0 = blockIdx.x * 128;
    int col0 = blockIdx.y * 128;
    int lane = tid & 31, wid = tid >> 5;
    int warp_m = wid & 1;
    int warp_n = wid >> 1;

    if (MODE == 1 || MODE == 2) {
        if (tid < DD) bn_coeff(1, gamma, beta, tid, scS[tid], shS[tid]);
        if (MODE == 2 && tid < 2 * DD) stS[tid] = 0.f;
        __syncthreads();
    }

    float4 c[4][4];
#pragma unroll
    for (int i = 0; i < 4; i++)
#pragma unroll
        for (int j = 0; j < 4; j++) c[i][j] = make_float4(0.f, 0.f, 0.f, 0.f);

    int la_r = tid >> 3;
    int la_k = (tid & 7) * 4;
    int lbk = tid & 7;
    int lbc = (tid >> 3) * 4;

    for (int kt = 0; kt < K; kt += 32) {
        // ---- A tile -> permuted smem ----
#pragma unroll
        for (int i = 0; i < 4; i++) {
            int r = la_r + i * 32;
            int m = row0 + r;
            float4 v = make_float4(0.f, 0.f, 0.f, 0.f);
            if (m < NN) v = *(const float4*)(A + (size_t)m * K + kt + la_k);
            if (MODE == 1) {
                int k0 = kt + la_k;
                v.x = scS[k0 + 0] * v.x + shS[k0 + 0];
                v.y = scS[k0 + 1] * v.y + shS[k0 + 1];
                v.z = scS[k0 + 2] * v.z + shS[k0 + 2];
                v.w = scS[k0 + 3] * v.w + shS[k0 + 3];
            }
            int s  = la_k >> 3;
            int am = r >> 4, rr = r & 15;
            int base = ((s * 8 + am) * 32 + (rr & 7) * 4) * 4 + (rr >> 3) + ((la_k >> 2) & 1) * 2;
            As[base + 0]  = f2tf32(v.x);
            As[base + 4]  = f2tf32(v.y);
            As[base + 8]  = f2tf32(v.z);
            As[base + 12] = f2tf32(v.w);
        }
        // ---- B tile -> permuted smem ----
#pragma unroll
        for (int i = 0; i < 4; i++) {
            int k = lbk + i * 8;
            float4 v = *(const float4*)(B + (size_t)(kt + k) * NLD + col0 + lbc);
            int s  = k >> 3;
            int bn = lbc >> 3;
            int c7 = lbc & 7;
            int base = ((s * 16 + bn) * 32 + c7 * 4 + (k & 3)) * 2 + ((k >> 2) & 1);
            Bs[base + 0]  = f2tf32(v.x);
            Bs[base + 8]  = f2tf32(v.y);
            Bs[base + 16] = f2tf32(v.z);
            Bs[base + 24] = f2tf32(v.w);
        }
        __syncthreads();
#pragma unroll
        for (int s = 0; s < 4; s++) {
            uint4 a[4];
            uint2 bf[4];
#pragma unroll
            for (int i = 0; i < 4; i++)
                a[i] = *(const uint4*)&As[((s * 8 + warp_m * 4 + i) * 32 + lane) * 4];
#pragma unroll
            for (int j = 0; j < 4; j++)
                bf[j] = *(const uint2*)&Bs[((s * 16 + warp_n * 4 + j) * 32 + lane) * 2];
#pragma unroll
            for (int i = 0; i < 4; i++)
#pragma unroll
                for (int j = 0; j < 4; j++)
                    mma_tf32(c[i][j], a[i], bf[j]);
        }
        __syncthreads();
    }

    // ---- epilogue ----
    int g = lane >> 2, tk = lane & 3;
    float sreg[8], qreg[8];
    if (MODE == 2) {
#pragma unroll
        for (int j = 0; j < 8; j++) { sreg[j] = 0.f; qreg[j] = 0.f; }
    }
#pragma unroll
    for (int i = 0; i < 4; i++) {
        int rx = row0 + warp_m * 64 + i * 16 + g;
        int rz = rx + 8;
        if (MODE == 0) {
#pragma unroll
            for (int j = 0; j < 4; j++) {
                int cc = col0 + warp_n * 32 + j * 8 + tk * 2;
                if (rx < NN) {
                    float2 v = make_float2(c[i][j].x, c[i][j].y);
                    *(float2*)&g_h[(size_t)rx * DD + cc] = v;
                }
                if (rz < NN) {
                    float2 v = make_float2(c[i][j].z, c[i][j].w);
                    *(float2*)&g_h[(size_t)rz * DD + cc] = v;
                }
            }
        } else if (MODE == 1) {
#pragma unroll
            for (int j = 0; j < 4; j++) {
                int cc = col0 + warp_n * 32 + j * 8 + tk * 2;
                float2 bv = *(const float2*)(bias + cc);
                if (rx < NN) {
                    float2 v = make_float2(fmaxf(c[i][j].x + bv.x, 0.f), fmaxf(c[i][j].y + bv.y, 0.f));
                    *(float2*)&g_u[(size_t)rx * 256 + cc] = v;
                }
                if (rz < NN) {
                    float2 v = make_float2(fmaxf(c[i][j].z + bv.x, 0.f), fmaxf(c[i][j].w + bv.y, 0.f));
                    *(float2*)&g_u[(size_t)rz * 256 + cc] = v;
                }
            }
        } else {
#pragma unroll
            for (int j = 0; j < 4; j++) {
                int cc = col0 + warp_n * 32 + j * 8 + tk * 2;
                float2 bv = *(const float2*)(bias + cc);
                float a0 = scS[cc], a1 = scS[cc + 1];
                float d0 = shS[cc], d1 = shS[cc + 1];
                if (rx < NN) {
                    float2 r = *(const float2*)&g_h[(size_t)rx * DD + cc];
                    float2 v = make_float2(c[i][j].x + bv.x + a0 * r.x + d0,
                                           c[i][j].y + bv.y + a1 * r.y + d1);
                    *(float2*)&g_h[(size_t)rx * DD + cc] = v;
                    sreg[j * 2] += v.x;     qreg[j * 2] += v.x * v.x;
                    sreg[j * 2 + 1] += v.y; qreg[j * 2 + 1] += v.y * v.y;
                }
                if (rz < NN) {
                    float2 r = *(const float2*)&g_h[(size_t)rz * DD + cc];
                    float2 v = make_float2(c[i][j].z + bv.x + a0 * r.x + d0,
                                           c[i][j].w + bv.y + a1 * r.y + d1);
                    *(float2*)&g_h[(size_t)rz * DD + cc] = v;
                    sreg[j * 2] += v.x;     qreg[j * 2] += v.x * v.x;
                    sreg[j * 2 + 1] += v.y; qreg[j * 2 + 1] += v.y * v.y;
                }
            }
        }
    }
    if (MODE == 2) {
#pragma unroll
        for (int j = 0; j < 4; j++) {
            int cc = warp_n * 32 + j * 8 + tk * 2;   // col0 == 0 for MODE 2
            atomicAdd(&stS[cc],          sreg[j * 2]);
            atomicAdd(&stS[cc + 1],      sreg[j * 2 + 1]);
            atomicAdd(&stS[DD + cc],     qreg[j * 2]);
            atomicAdd(&stS[DD + cc + 1], qreg[j * 2 + 1]);
        }
        __syncthreads();
        if (tid < DD) {
            atomicAdd(&g_sum[2 * DD + tid], stS[tid]);
            atomicAdd(&g_sq[2 * DD + tid], stS[DD + tid]);
        }
    }
}

// ---------------- stats helper (block reduce + global atomic) ----------------
__device__ __forceinline__ void stats_reduce(int set, int lane,
                                             float s0, float s1, float s2, float s3,
                                             float q0, float q1, float q2, float q3) {
    __shared__ float ss[DD], sq[DD];
    if (threadIdx.x < DD) { ss[threadIdx.x] = 0.f; sq[threadIdx.x] = 0.f; }
    __syncthreads();
    int c = lane * 4;
    atomicAdd(&ss[c + 0], s0); atomicAdd(&ss[c + 1], s1);
    atomicAdd(&ss[c + 2], s2); atomicAdd(&ss[c + 3], s3);
    atomicAdd(&sq[c + 0], q0); atomicAdd(&sq[c + 1], q1);
    atomicAdd(&sq[c + 2], q2); atomicAdd(&sq[c + 3], q3);
    __syncthreads();
    if (threadIdx.x < DD) {
        atomicAdd(&g_sum[set * DD + threadIdx.x], ss[threadIdx.x]);
        atomicAdd(&g_sq[set * DD + threadIdx.x], sq[threadIdx.x]);
    }
}

// ---------------- CSR gather ----------------
// t[n] = dinv[n] * ( h[n]*dinv[n] + sum_s h[s]*dinv[s] ) + b   -> g_acc, stats set 0
__global__ __launch_bounds__(256) void gather_kernel(const float* __restrict__ b) {
    int gw = (blockIdx.x * blockDim.x + threadIdx.x) >> 5;
    int lane = threadIdx.x & 31;
    int nw = (gridDim.x * blockDim.x) >> 5;
    float4 bb = *(const float4*)(b + lane * 4);
    float s0 = 0, s1 = 0, s2 = 0, s3 = 0, q0 = 0, q1 = 0, q2 = 0, q3 = 0;
    for (int n = gw; n < NN; n += nw) {
        int st = g_off[n];
        int en = g_cursor[n];             // off[n] + cnt[n]
        float dv = g_dinv[n];
        size_t base = (size_t)n * DD + lane * 4;
        float4 hv = *(const float4*)&g_h[base];   // self loop term * dinv[n]
        float4 acc;
        acc.x = hv.x * dv; acc.y = hv.y * dv; acc.z = hv.z * dv; acc.w = hv.w * dv;
        int j = st;
        for (; j + 1 < en; j += 2) {
            int sA = g_srcs[j], sB = g_srcs[j + 1];
            float dA = g_dinv[sA], dB = g_dinv[sB];
            float4 vA = *(const float4*)&g_h[(size_t)sA * DD + lane * 4];
            float4 vB = *(const float4*)&g_h[(size_t)sB * DD + lane * 4];
            acc.x += vA.x * dA + vB.x * dB; acc.y += vA.y * dA + vB.y * dB;
            acc.z += vA.z * dA + vB.z * dB; acc.w += vA.w * dA + vB.w * dB;
        }
        if (j < en) {
            int sA = g_srcs[j];
            float dA = g_dinv[sA];
            float4 vA = *(const float4*)&g_h[(size_t)sA * DD + lane * 4];
            acc.x += vA.x * dA; acc.y += vA.y * dA; acc.z += vA.z * dA; acc.w += vA.w * dA;
        }
        float4 t;
        t.x = acc.x * dv + bb.x; t.y = acc.y * dv + bb.y;
        t.z = acc.z * dv + bb.z; t.w = acc.w * dv + bb.w;
        *(float4*)&g_acc[base] = t;
        s0 += t.x; s1 += t.y; s2 += t.z; s3 += t.w;
        q0 += t.x * t.x; q1 += t.y * t.y; q2 += t.z * t.z; q3 += t.w * t.w;
    }
    stats_reduce(0, lane, s0, s1, s2, s3, q0, q1, q2, q3);
}

// ---------------- h2 = x + relu(bn1(t)) -> g_h, stats set 1 ----------------
__global__ __launch_bounds__(256) void passB_kernel(const float* __restrict__ x,
                                                    const float* __restrict__ gamma1,
                                                    const float* __restrict__ beta1) {
    int gt = blockIdx.x * blockDim.x + threadIdx.x;
    int gw = gt >> 5, lane = threadIdx.x & 31;
    int nw = (gridDim.x * blockDim.x) >> 5;
    int c = lane * 4;
    float sc0, sh0, sc1, sh1, sc2, sh2, sc3, sh3;
    bn_coeff(0, gamma1, beta1, c + 0, sc0, sh0);
    bn_coeff(0, gamma1, beta1, c + 1, sc1, sh1);
    bn_coeff(0, gamma1, beta1, c + 2, sc2, sh2);
    bn_coeff(0, gamma1, beta1, c + 3, sc3, sh3);
    float s0 = 0, s1 = 0, s2 = 0, s3 = 0, q0 = 0, q1 = 0, q2 = 0, q3 = 0;
    for (int r = gw; r < NN; r += nw) {
        size_t off = (size_t)r * DD + c;
        float4 t  = *(const float4*)&g_acc[off];
        float4 xv = *(const float4*)(x + off);
        float4 v;
        v.x = xv.x + fmaxf(sc0 * t.x + sh0, 0.f);
        v.y = xv.y + fmaxf(sc1 * t.y + sh1, 0.f);
        v.z = xv.z + fmaxf(sc2 * t.z + sh2, 0.f);
        v.w = xv.w + fmaxf(sc3 * t.w + sh3, 0.f);
        *(float4*)&g_h[off] = v;
        s0 += v.x; s1 += v.y; s2 += v.z; s3 += v.w;
        q0 += v.x * v.x; q1 += v.y * v.y; q2 += v.z * v.z; q3 += v.w * v.w;
    }
    stats_reduce(1, lane, s0, s1, s2, s3, q0, q1, q2, q3);
}

// ---------------- out = bn3(h3) ----------------
__global__ __launch_bounds__(256) void final_kernel(float* __restrict__ out,
                                                    const float* __restrict__ gamma3,
                                                    const float* __restrict__ beta3) {
    int c = (threadIdx.x & 31) * 4;
    float sc0, sh0, sc1, sh1, sc2, sh2, sc3, sh3;
    bn_coeff(2, gamma3, beta3, c + 0, sc0, sh0);
    bn_coeff(2, gamma3, beta3, c + 1, sc1, sh1);
    bn_coeff(2, gamma3, beta3, c + 2, sc2, sh2);
    bn_coeff(2, gamma3, beta3, c + 3, sc3, sh3);
    int total = NN * (DD / 4);
    for (int f = blockIdx.x * blockDim.x + threadIdx.x; f < total; f += gridDim.x * blockDim.x) {
        float4 h = ((const float4*)g_h)[f];
        float4 v;
        v.x = sc0 * h.x + sh0;
        v.y = sc1 * h.y + sh1;
        v.z = sc2 * h.z + sh2;
        v.w = sc3 * h.w + sh3;
        ((float4*)out)[f] = v;
    }
}

// ---------------- host ----------------
extern "C" void kernel_launch(void* const* d_in, const int* in_sizes, int n_in,
                              void* d_out, int out_size) {
    const float* x      = (const float*)d_in[0];
    const int*   ei     = (const int*)  d_in[1];
    const float* W      = (const float*)d_in[2];
    const float* b      = (const float*)d_in[3];
    const float* gamma1 = (const float*)d_in[4];
    const float* beta1  = (const float*)d_in[5];
    const float* gamma2 = (const float*)d_in[6];
    const float* beta2  = (const float*)d_in[7];
    const float* gamma3 = (const float*)d_in[8];
    const float* beta3  = (const float*)d_in[9];
    const float* W1     = (const float*)d_in[10];
    const float* b1     = (const float*)d_in[11];
    const float* W2     = (const float*)d_in[12];
    const float* b2     = (const float*)d_in[13];
    float* out = (float*)d_out;
    int E = in_sizes[1] / 2;

    // resource handles (created once; identical GPU work issued on every call)
    static cudaStream_t s2 = nullptr;
    static cudaEvent_t evFork = nullptr, evJoin = nullptr;
    if (s2 == nullptr) {
        cudaStreamCreateWithFlags(&s2, cudaStreamNonBlocking);
        cudaEventCreateWithFlags(&evFork, cudaEventDisableTiming);
        cudaEventCreateWithFlags(&evJoin, cudaEventDisableTiming);
    }

    // fork: CSR build on s2 overlaps gemm0 on the main stream.
    // gemm0 (MODE 0) touches only x, W, g_h — disjoint from everything s2 writes.
    cudaEventRecord(evFork, 0);
    cudaStreamWaitEvent(s2, evFork, 0);

    init_kernel<<<(NN + 255) / 256, 256, 0, s2>>>();
    count_kernel<<<(E + 255) / 256, 256, 0, s2>>>(ei, E);
    scan1_kernel<<<NBLK_SCAN, 256, 0, s2>>>();
    scan3_kernel<<<(NN + 255) / 256, 256, 0, s2>>>();
    fill_kernel<<<(E + 255) / 256, 256, 0, s2>>>(ei, E);

    gemm_tc<0, 128, 128><<<dim3((NN + 127) / 128, 1), 256>>>(x, W, nullptr, nullptr, nullptr);

    cudaEventRecord(evJoin, s2);
    cudaStreamWaitEvent(0, evJoin, 0);

    gather_kernel<<<2048, 256>>>(b);
    passB_kernel<<<1024, 256>>>(x, gamma1, beta1);
    gemm_tc<1, 128, 256><<<dim3((NN + 127) / 128, 2), 256>>>(nullptr, W1, b1, gamma2, beta2);
    gemm_tc<2, 256, 128><<<dim3((NN + 127) / 128, 1), 256>>>(nullptr, W2, b2, gamma2, beta2);
    final_kernel<<<2048, 256>>>(out, gamma3, beta3);
}

// round 12
// speedup vs baseline: 1.0595x; 1.0595x over previous
#include <cuda_runtime.h>
#include <cstdint>

#define NN 100000
#define DD 128
#define EPS 1e-5f
#define EMAX 3200000
#define NBLK_SCAN 98   // ceil(NN/1024)

// ---------------- device scratch (no allocations allowed) ----------------
__device__ float g_h[(size_t)NN * DD];     // hs = (x@W)*dinv[row]; then h2; then h3
__device__ float g_acc[(size_t)NN * DD];   // t
__device__ float g_u[(size_t)NN * 256];    // FFN hidden
__device__ float g_dinv[NN];
__device__ int   g_cnt[NN];
__device__ int   g_off[NN];
__device__ int   g_cursor[NN];
__device__ int   g_bsum[NBLK_SCAN];
__device__ int   g_srcs[EMAX];
__device__ float g_sum[3 * DD];
__device__ float g_sq[3 * DD];

// ---------------- small helpers ----------------
__device__ __forceinline__ float f2tf32(float x) {
    uint32_t u;
    asm("cvt.rna.tf32.f32 %0, %1;" : "=r"(u) : "f"(x));
    return __uint_as_float(u);
}

__device__ __forceinline__ void mma_tf32(float4& d, const uint4& a, const uint2& b) {
    asm volatile(
        "mma.sync.aligned.m16n8k8.row.col.f32.tf32.tf32.f32 "
        "{%0,%1,%2,%3}, {%4,%5,%6,%7}, {%8,%9}, {%0,%1,%2,%3};"
        : "+f"(d.x), "+f"(d.y), "+f"(d.z), "+f"(d.w)
        : "r"(a.x), "r"(a.y), "r"(a.z), "r"(a.w), "r"(b.x), "r"(b.y));
}

// compute BN affine coeffs for column c of stats set `set`
__device__ __forceinline__ void bn_coeff(int set, const float* __restrict__ gamma,
                                         const float* __restrict__ beta,
                                         int c, float& sc, float& sh) {
    float m = g_sum[set * DD + c] * (1.0f / NN);
    float v = g_sq[set * DD + c] * (1.0f / NN) - m * m;
    float rs = rsqrtf(v + EPS);
    sc = gamma[c] * rs;
    sh = beta[c] - sc * m;
}

// ---------------- init / degree / CSR build ----------------
__global__ void init_kernel() {
    int i = blockIdx.x * blockDim.x + threadIdx.x;
    if (i < NN) g_cnt[i] = 0;
    if (i < 3 * DD) { g_sum[i] = 0.f; g_sq[i] = 0.f; }
}

__global__ void count_kernel(const int* __restrict__ ei, int E) {
    int e = blockIdx.x * blockDim.x + threadIdx.x;
    if (e < E) atomicAdd(&g_cnt[ei[E + e]], 1);
}

__global__ void scan1_kernel() {
    __shared__ int sh[256];
    int blk = blockIdx.x, tid = threadIdx.x;
    int i0 = blk * 1024 + tid * 4;
    int c0 = (i0 + 0 < NN) ? g_cnt[i0 + 0] : 0;
    int c1 = (i0 + 1 < NN) ? g_cnt[i0 + 1] : 0;
    int c2 = (i0 + 2 < NN) ? g_cnt[i0 + 2] : 0;
    int c3 = (i0 + 3 < NN) ? g_cnt[i0 + 3] : 0;
    int s = c0 + c1 + c2 + c3;
    sh[tid] = s;
    __syncthreads();
    for (int off = 1; off < 256; off <<= 1) {
        int v = (tid >= off) ? sh[tid - off] : 0;
        __syncthreads();
        sh[tid] += v;
        __syncthreads();
    }
    int excl = sh[tid] - s;
    if (tid == 255) g_bsum[blk] = sh[255];
    if (i0 + 0 < NN) g_off[i0 + 0] = excl;
    if (i0 + 1 < NN) g_off[i0 + 1] = excl + c0;
    if (i0 + 2 < NN) g_off[i0 + 2] = excl + c0 + c1;
    if (i0 + 3 < NN) g_off[i0 + 3] = excl + c0 + c1 + c2;
}

// folds the block-sum exclusive scan into each thread (bsum staged in smem)
__global__ void scan3_kernel() {
    __shared__ int bs[NBLK_SCAN];
    if (threadIdx.x < NBLK_SCAN) bs[threadIdx.x] = g_bsum[threadIdx.x];
    __syncthreads();
    int i = blockIdx.x * blockDim.x + threadIdx.x;
    if (i < NN) {
        int q = i >> 10;
        int base = 0;
        for (int j = 0; j < q; j++) base += bs[j];
        int v = g_off[i] + base;
        g_off[i] = v;
        g_cursor[i] = v;
        g_dinv[i] = rsqrtf(1.0f + (float)g_cnt[i]);   // self loop included
    }
}

__global__ void fill_kernel(const int* __restrict__ ei, int E) {
    int e = blockIdx.x * blockDim.x + threadIdx.x;
    if (e < E) {
        int d = ei[E + e];
        int p = atomicAdd(&g_cursor[d], 1);
        g_srcs[p] = ei[e];
    }
}

// ---------------- tf32 tensor-core GEMM ----------------
// Tile 128x128, BK=32, 256 threads = 8 warps (2x4), warp tile 64x32.
// MODE 0: g_h = (x @ W) * dinv[row]                           (K=128, NLD=128)
// MODE 1: g_u = relu(affine1(g_h) @ W1 + b1)                  (K=128, NLD=256)
// MODE 2: g_h = g_u @ W2 + b2 + affine1(g_h); stats set 2     (K=256, NLD=128)
template<int MODE, int K, int NLD>
__global__ __launch_bounds__(256) void gemm_tc(const float* __restrict__ Ax,
                                               const float* __restrict__ B,
                                               const float* __restrict__ bias,
                                               const float* __restrict__ gamma,
                                               const float* __restrict__ beta)
{
    __shared__ __align__(16) float As[4096];  // [slice(4)][am(8)][lane(32)][reg(4)]
    __shared__ __align__(16) float Bs[4096];  // [slice(4)][bn(16)][lane(32)][reg(2)]
    __shared__ float scS[DD], shS[DD];
    __shared__ float stS[2 * DD];
    const float* A = (MODE == 0) ? Ax : (MODE == 1 ? (const float*)g_h : (const float*)g_u);

    int tid = threadIdx.x;
    int row0 = blockIdx.x * 128;
    int col0 = blockIdx.y * 128;
    int lane = tid & 31, wid = tid >> 5;
    int warp_m = wid & 1;
    int warp_n = wid >> 1;

    if (MODE == 1 || MODE == 2) {
        if (tid < DD) bn_coeff(1, gamma, beta, tid, scS[tid], shS[tid]);
        if (MODE == 2 && tid < 2 * DD) stS[tid] = 0.f;
        __syncthreads();
    }

    float4 c[4][4];
#pragma unroll
    for (int i = 0; i < 4; i++)
#pragma unroll
        for (int j = 0; j < 4; j++) c[i][j] = make_float4(0.f, 0.f, 0.f, 0.f);

    int la_r = tid >> 3;
    int la_k = (tid & 7) * 4;
    int lbk = tid & 7;
    int lbc = (tid >> 3) * 4;

    for (int kt = 0; kt < K; kt += 32) {
        // ---- A tile -> permuted smem ----
#pragma unroll
        for (int i = 0; i < 4; i++) {
            int r = la_r + i * 32;
            int m = row0 + r;
            float4 v = make_float4(0.f, 0.f, 0.f, 0.f);
            if (m < NN) v = *(const float4*)(A + (size_t)m * K + kt + la_k);
            if (MODE == 1) {
                int k0 = kt + la_k;
                v.x = scS[k0 + 0] * v.x + shS[k0 + 0];
                v.y = scS[k0 + 1] * v.y + shS[k0 + 1];
                v.z = scS[k0 + 2] * v.z + shS[k0 + 2];
                v.w = scS[k0 + 3] * v.w + shS[k0 + 3];
            }
            int s  = la_k >> 3;
            int am = r >> 4, rr = r & 15;
            int base = ((s * 8 + am) * 32 + (rr & 7) * 4) * 4 + (rr >> 3) + ((la_k >> 2) & 1) * 2;
            As[base + 0]  = f2tf32(v.x);
            As[base + 4]  = f2tf32(v.y);
            As[base + 8]  = f2tf32(v.z);
            As[base + 12] = f2tf32(v.w);
        }
        // ---- B tile -> permuted smem ----
#pragma unroll
        for (int i = 0; i < 4; i++) {
            int k = lbk + i * 8;
            float4 v = *(const float4*)(B + (size_t)(kt + k) * NLD + col0 + lbc);
            int s  = k >> 3;
            int bn = lbc >> 3;
            int c7 = lbc & 7;
            int base = ((s * 16 + bn) * 32 + c7 * 4 + (k & 3)) * 2 + ((k >> 2) & 1);
            Bs[base + 0]  = f2tf32(v.x);
            Bs[base + 8]  = f2tf32(v.y);
            Bs[base + 16] = f2tf32(v.z);
            Bs[base + 24] = f2tf32(v.w);
        }
        __syncthreads();
#pragma unroll
        for (int s = 0; s < 4; s++) {
            uint4 a[4];
            uint2 bf[4];
#pragma unroll
            for (int i = 0; i < 4; i++)
                a[i] = *(const uint4*)&As[((s * 8 + warp_m * 4 + i) * 32 + lane) * 4];
#pragma unroll
            for (int j = 0; j < 4; j++)
                bf[j] = *(const uint2*)&Bs[((s * 16 + warp_n * 4 + j) * 32 + lane) * 2];
#pragma unroll
            for (int i = 0; i < 4; i++)
#pragma unroll
                for (int j = 0; j < 4; j++)
                    mma_tf32(c[i][j], a[i], bf[j]);
        }
        __syncthreads();
    }

    // ---- epilogue ----
    int g = lane >> 2, tk = lane & 3;
    float sreg[8], qreg[8];
    if (MODE == 2) {
#pragma unroll
        for (int j = 0; j < 8; j++) { sreg[j] = 0.f; qreg[j] = 0.f; }
    }
#pragma unroll
    for (int i = 0; i < 4; i++) {
        int rx = row0 + warp_m * 64 + i * 16 + g;
        int rz = rx + 8;
        if (MODE == 0) {
            float dx = (rx < NN) ? g_dinv[rx] : 0.f;
            float dz = (rz < NN) ? g_dinv[rz] : 0.f;
#pragma unroll
            for (int j = 0; j < 4; j++) {
                int cc = col0 + warp_n * 32 + j * 8 + tk * 2;
                if (rx < NN) {
                    float2 v = make_float2(c[i][j].x * dx, c[i][j].y * dx);
                    *(float2*)&g_h[(size_t)rx * DD + cc] = v;
                }
                if (rz < NN) {
                    float2 v = make_float2(c[i][j].z * dz, c[i][j].w * dz);
                    *(float2*)&g_h[(size_t)rz * DD + cc] = v;
                }
            }
        } else if (MODE == 1) {
#pragma unroll
            for (int j = 0; j < 4; j++) {
                int cc = col0 + warp_n * 32 + j * 8 + tk * 2;
                float2 bv = *(const float2*)(bias + cc);
                if (rx < NN) {
                    float2 v = make_float2(fmaxf(c[i][j].x + bv.x, 0.f), fmaxf(c[i][j].y + bv.y, 0.f));
                    *(float2*)&g_u[(size_t)rx * 256 + cc] = v;
                }
                if (rz < NN) {
                    float2 v = make_float2(fmaxf(c[i][j].z + bv.x, 0.f), fmaxf(c[i][j].w + bv.y, 0.f));
                    *(float2*)&g_u[(size_t)rz * 256 + cc] = v;
                }
            }
        } else {
#pragma unroll
            for (int j = 0; j < 4; j++) {
                int cc = col0 + warp_n * 32 + j * 8 + tk * 2;
                float2 bv = *(const float2*)(bias + cc);
                float a0 = scS[cc], a1 = scS[cc + 1];
                float d0 = shS[cc], d1 = shS[cc + 1];
                if (rx < NN) {
                    float2 r = *(const float2*)&g_h[(size_t)rx * DD + cc];
                    float2 v = make_float2(c[i][j].x + bv.x + a0 * r.x + d0,
                                           c[i][j].y + bv.y + a1 * r.y + d1);
                    *(float2*)&g_h[(size_t)rx * DD + cc] = v;
                    sreg[j * 2] += v.x;     qreg[j * 2] += v.x * v.x;
                    sreg[j * 2 + 1] += v.y; qreg[j * 2 + 1] += v.y * v.y;
                }
                if (rz < NN) {
                    float2 r = *(const float2*)&g_h[(size_t)rz * DD + cc];
                    float2 v = make_float2(c[i][j].z + bv.x + a0 * r.x + d0,
                                           c[i][j].w + bv.y + a1 * r.y + d1);
                    *(float2*)&g_h[(size_t)rz * DD + cc] = v;
                    sreg[j * 2] += v.x;     qreg[j * 2] += v.x * v.x;
                    sreg[j * 2 + 1] += v.y; qreg[j * 2 + 1] += v.y * v.y;
                }
            }
        }
    }
    if (MODE == 2) {
#pragma unroll
        for (int j = 0; j < 4; j++) {
            int cc = warp_n * 32 + j * 8 + tk * 2;   // col0 == 0 for MODE 2
            atomicAdd(&stS[cc],          sreg[j * 2]);
            atomicAdd(&stS[cc + 1],      sreg[j * 2 + 1]);
            atomicAdd(&stS[DD + cc],     qreg[j * 2]);
            atomicAdd(&stS[DD + cc + 1], qreg[j * 2 + 1]);
        }
        __syncthreads();
        if (tid < DD) {
            atomicAdd(&g_sum[2 * DD + tid], stS[tid]);
            atomicAdd(&g_sq[2 * DD + tid], stS[DD + tid]);
        }
    }
}

// ---------------- stats helper (block reduce + global atomic) ----------------
__device__ __forceinline__ void stats_reduce(int set, int lane,
                                             float s0, float s1, float s2, float s3,
                                             float q0, float q1, float q2, float q3) {
    __shared__ float ss[DD], sq[DD];
    if (threadIdx.x < DD) { ss[threadIdx.x] = 0.f; sq[threadIdx.x] = 0.f; }
    __syncthreads();
    int c = lane * 4;
    atomicAdd(&ss[c + 0], s0); atomicAdd(&ss[c + 1], s1);
    atomicAdd(&ss[c + 2], s2); atomicAdd(&ss[c + 3], s3);
    atomicAdd(&sq[c + 0], q0); atomicAdd(&sq[c + 1], q1);
    atomicAdd(&sq[c + 2], q2); atomicAdd(&sq[c + 3], q3);
    __syncthreads();
    if (threadIdx.x < DD) {
        atomicAdd(&g_sum[set * DD + threadIdx.x], ss[threadIdx.x]);
        atomicAdd(&g_sq[set * DD + threadIdx.x], sq[threadIdx.x]);
    }
}

// ---------------- CSR gather: t[n] = (hs[n] + sum_s hs[s]) * dinv[n] + b ----------------
__global__ __launch_bounds__(256) void gather_kernel(const float* __restrict__ b) {
    int gw = (blockIdx.x * blockDim.x + threadIdx.x) >> 5;
    int lane = threadIdx.x & 31;
    int nw = (gridDim.x * blockDim.x) >> 5;
    float4 bb = *(const float4*)(b + lane * 4);
    float s0 = 0, s1 = 0, s2 = 0, s3 = 0, q0 = 0, q1 = 0, q2 = 0, q3 = 0;
    for (int n = gw; n < NN; n += nw) {
        int st = g_off[n];
        int en = g_cursor[n];             // off[n] + cnt[n]
        size_t base = (size_t)n * DD + lane * 4;
        float4 acc = *(const float4*)&g_h[base];   // self loop term (pre-scaled)
        int j = st;
        for (; j + 1 < en; j += 2) {
            int sA = g_srcs[j], sB = g_srcs[j + 1];
            float4 vA = *(const float4*)&g_h[(size_t)sA * DD + lane * 4];
            float4 vB = *(const float4*)&g_h[(size_t)sB * DD + lane * 4];
            acc.x += vA.x + vB.x; acc.y += vA.y + vB.y;
            acc.z += vA.z + vB.z; acc.w += vA.w + vB.w;
        }
        if (j < en) {
            int sA = g_srcs[j];
            float4 vA = *(const float4*)&g_h[(size_t)sA * DD + lane * 4];
            acc.x += vA.x; acc.y += vA.y; acc.z += vA.z; acc.w += vA.w;
        }
        float dv = g_dinv[n];
        float4 t;
        t.x = acc.x * dv + bb.x; t.y = acc.y * dv + bb.y;
        t.z = acc.z * dv + bb.z; t.w = acc.w * dv + bb.w;
        *(float4*)&g_acc[base] = t;
        s0 += t.x; s1 += t.y; s2 += t.z; s3 += t.w;
        q0 += t.x * t.x; q1 += t.y * t.y; q2 += t.z * t.z; q3 += t.w * t.w;
    }
    stats_reduce(0, lane, s0, s1, s2, s3, q0, q1, q2, q3);
}

// ---------------- h2 = x + relu(bn1(t)) -> g_h, stats set 1 ----------------
__global__ __launch_bounds__(256) void passB_kernel(const float* __restrict__ x,
                                                    const float* __restrict__ gamma1,
                                                    const float* __restrict__ beta1) {
    int gt = blockIdx.x * blockDim.x + threadIdx.x;
    int gw = gt >> 5, lane = threadIdx.x & 31;
    int nw = (gridDim.x * blockDim.x) >> 5;
    int c = lane * 4;
    float sc0, sh0, sc1, sh1, sc2, sh2, sc3, sh3;
    bn_coeff(0, gamma1, beta1, c + 0, sc0, sh0);
    bn_coeff(0, gamma1, beta1, c + 1, sc1, sh1);
    bn_coeff(0, gamma1, beta1, c + 2, sc2, sh2);
    bn_coeff(0, gamma1, beta1, c + 3, sc3, sh3);
    float s0 = 0, s1 = 0, s2 = 0, s3 = 0, q0 = 0, q1 = 0, q2 = 0, q3 = 0;
    for (int r = gw; r < NN; r += nw) {
        size_t off = (size_t)r * DD + c;
        float4 t  = *(const float4*)&g_acc[off];
        float4 xv = *(const float4*)(x + off);
        float4 v;
        v.x = xv.x + fmaxf(sc0 * t.x + sh0, 0.f);
        v.y = xv.y + fmaxf(sc1 * t.y + sh1, 0.f);
        v.z = xv.z + fmaxf(sc2 * t.z + sh2, 0.f);
        v.w = xv.w + fmaxf(sc3 * t.w + sh3, 0.f);
        *(float4*)&g_h[off] = v;
        s0 += v.x; s1 += v.y; s2 += v.z; s3 += v.w;
        q0 += v.x * v.x; q1 += v.y * v.y; q2 += v.z * v.z; q3 += v.w * v.w;
    }
    stats_reduce(1, lane, s0, s1, s2, s3, q0, q1, q2, q3);
}

// ---------------- out = bn3(h3) ----------------
__global__ __launch_bounds__(256) void final_kernel(float* __restrict__ out,
                                                    const float* __restrict__ gamma3,
                                                    const float* __restrict__ beta3) {
    int c = (threadIdx.x & 31) * 4;
    float sc0, sh0, sc1, sh1, sc2, sh2, sc3, sh3;
    bn_coeff(2, gamma3, beta3, c + 0, sc0, sh0);
    bn_coeff(2, gamma3, beta3, c + 1, sc1, sh1);
    bn_coeff(2, gamma3, beta3, c + 2, sc2, sh2);
    bn_coeff(2, gamma3, beta3, c + 3, sc3, sh3);
    int total = NN * (DD / 4);
    for (int f = blockIdx.x * blockDim.x + threadIdx.x; f < total; f += gridDim.x * blockDim.x) {
        float4 h = ((const float4*)g_h)[f];
        float4 v;
        v.x = sc0 * h.x + sh0;
        v.y = sc1 * h.y + sh1;
        v.z = sc2 * h.z + sh2;
        v.w = sc3 * h.w + sh3;
        ((float4*)out)[f] = v;
    }
}

// ---------------- host (single stream, fully serial) ----------------
extern "C" void kernel_launch(void* const* d_in, const int* in_sizes, int n_in,
                              void* d_out, int out_size) {
    const float* x      = (const float*)d_in[0];
    const int*   ei     = (const int*)  d_in[1];
    const float* W      = (const float*)d_in[2];
    const float* b      = (const float*)d_in[3];
    const float* gamma1 = (const float*)d_in[4];
    const float* beta1  = (const float*)d_in[5];
    const float* gamma2 = (const float*)d_in[6];
    const float* beta2  = (const float*)d_in[7];
    const float* gamma3 = (const float*)d_in[8];
    const float* beta3  = (const float*)d_in[9];
    const float* W1     = (const float*)d_in[10];
    const float* b1     = (const float*)d_in[11];
    const float* W2     = (const float*)d_in[12];
    const float* b2     = (const float*)d_in[13];
    float* out = (float*)d_out;
    int E = in_sizes[1] / 2;

    init_kernel<<<(NN + 255) / 256, 256>>>();
    count_kernel<<<(E + 255) / 256, 256>>>(ei, E);
    scan1_kernel<<<NBLK_SCAN, 256>>>();
    scan3_kernel<<<(NN + 255) / 256, 256>>>();
    fill_kernel<<<(E + 255) / 256, 256>>>(ei, E);

    gemm_tc<0, 128, 128><<<dim3((NN + 127) / 128, 1), 256>>>(x, W, nullptr, nullptr, nullptr);
    gather_kernel<<<2048, 256>>>(b);
    passB_kernel<<<1024, 256>>>(x, gamma1, beta1);
    gemm_tc<1, 128, 256><<<dim3((NN + 127) / 128, 2), 256>>>(nullptr, W1, b1, gamma2, beta2);
    gemm_tc<2, 256, 128><<<dim3((NN + 127) / 128, 1), 256>>>(nullptr, W2, b2, gamma2, beta2);
    final_kernel<<<2048, 256>>>(out, gamma3, beta3);
}

// round 17
// speedup vs baseline: 1.1106x; 1.0483x over previous
#include <cuda_runtime.h>
#include <cuda_fp16.h>
#include <cstdint>

#define NN 100000
#define DD 128
#define EPS 1e-5f
#define EMAX 3200000
#define NBLK_SCAN 98   // ceil(NN/1024)

// ---------------- device scratch (no allocations allowed) ----------------
__device__ float  g_h[(size_t)NN * DD];     // h2 (from passB); then h3
__device__ __half g_hh[(size_t)NN * DD];    // hs = (x@W)*dinv[row] in fp16 (gather input)
__device__ float  g_acc[(size_t)NN * DD];   // t
__device__ float  g_u[(size_t)NN * 256];    // FFN hidden
__device__ float  g_dinv[NN];
__device__ int    g_cnt[NN];
__device__ int    g_off[NN];
__device__ int    g_cursor[NN];
__device__ int    g_bsum[NBLK_SCAN];
__device__ int    g_srcs[EMAX];
__device__ float  g_sum[3 * DD];
__device__ float  g_sq[3 * DD];

// ---------------- small helpers ----------------
__device__ __forceinline__ float f2tf32(float x) {
    uint32_t u;
    asm("cvt.rna.tf32.f32 %0, %1;" : "=r"(u) : "f"(x));
    return __uint_as_float(u);
}

__device__ __forceinline__ void mma_tf32(float4& d, const uint4& a, const uint2& b) {
    asm volatile(
        "mma.sync.aligned.m16n8k8.row.col.f32.tf32.tf32.f32 "
        "{%0,%1,%2,%3}, {%4,%5,%6,%7}, {%8,%9}, {%0,%1,%2,%3};"
        : "+f"(d.x), "+f"(d.y), "+f"(d.z), "+f"(d.w)
        : "r"(a.x), "r"(a.y), "r"(a.z), "r"(a.w), "r"(b.x), "r"(b.y));
}

// compute BN affine coeffs for column c of stats set `set`
__device__ __forceinline__ void bn_coeff(int set, const float* __restrict__ gamma,
                                         const float* __restrict__ beta,
                                         int c, float& sc, float& sh) {
    float m = g_sum[set * DD + c] * (1.0f / NN);
    float v = g_sq[set * DD + c] * (1.0f / NN) - m * m;
    float rs = rsqrtf(v + EPS);
    sc = gamma[c] * rs;
    sh = beta[c] - sc * m;
}

// ---------------- init / degree / CSR build ----------------
__global__ void init_kernel() {
    int i = blockIdx.x * blockDim.x + threadIdx.x;
    if (i < NN) g_cnt[i] = 0;
    if (i < 3 * DD) { g_sum[i] = 0.f; g_sq[i] = 0.f; }
}

__global__ void count_kernel(const int* __restrict__ ei, int E) {
    int e = blockIdx.x * blockDim.x + threadIdx.x;
    if (e < E) atomicAdd(&g_cnt[ei[E + e]], 1);
}

__global__ void scan1_kernel() {
    __shared__ int sh[256];
    int blk = blockIdx.x, tid = threadIdx.x;
    int i0 = blk * 1024 + tid * 4;
    int c0 = (i0 + 0 < NN) ? g_cnt[i0 + 0] : 0;
    int c1 = (i0 + 1 < NN) ? g_cnt[i0 + 1] : 0;
    int c2 = (i0 + 2 < NN) ? g_cnt[i0 + 2] : 0;
    int c3 = (i0 + 3 < NN) ? g_cnt[i0 + 3] : 0;
    int s = c0 + c1 + c2 + c3;
    sh[tid] = s;
    __syncthreads();
    for (int off = 1; off < 256; off <<= 1) {
        int v = (tid >= off) ? sh[tid - off] : 0;
        __syncthreads();
        sh[tid] += v;
        __syncthreads();
    }
    int excl = sh[tid] - s;
    if (tid == 255) g_bsum[blk] = sh[255];
    if (i0 + 0 < NN) g_off[i0 + 0] = excl;
    if (i0 + 1 < NN) g_off[i0 + 1] = excl + c0;
    if (i0 + 2 < NN) g_off[i0 + 2] = excl + c0 + c1;
    if (i0 + 3 < NN) g_off[i0 + 3] = excl + c0 + c1 + c2;
}

// folds the block-sum exclusive scan into each thread (bsum staged in smem)
__global__ void scan3_kernel() {
    __shared__ int bs[NBLK_SCAN];
    if (threadIdx.x < NBLK_SCAN) bs[threadIdx.x] = g_bsum[threadIdx.x];
    __syncthreads();
    int i = blockIdx.x * blockDim.x + threadIdx.x;
    if (i < NN) {
        int q = i >> 10;
        int base = 0;
        for (int j = 0; j < q; j++) base += bs[j];
        int v = g_off[i] + base;
        g_off[i] = v;
        g_cursor[i] = v;
        g_dinv[i] = rsqrtf(1.0f + (float)g_cnt[i]);   // self loop included
    }
}

__global__ void fill_kernel(const int* __restrict__ ei, int E) {
    int e = blockIdx.x * blockDim.x + threadIdx.x;
    if (e < E) {
        int d = ei[E + e];
        int p = atomicAdd(&g_cursor[d], 1);
        g_srcs[p] = ei[e];
    }
}

// ---------------- tf32 tensor-core GEMM ----------------
// Tile 128x128, BK=32, 256 threads = 8 warps (2x4), warp tile 64x32.
// MODE 0: g_hh = fp16( (x @ W) * dinv[row] )                  (K=128, NLD=128)
// MODE 1: g_u = relu(affine1(g_h) @ W1 + b1)                  (K=128, NLD=256)
// MODE 2: g_h = g_u @ W2 + b2 + affine1(g_h); stats set 2     (K=256, NLD=128)
template<int MODE, int K, int NLD>
__global__ __launch_bounds__(256) void gemm_tc(const float* __restrict__ Ax,
                                               const float* __restrict__ B,
                                               const float* __restrict__ bias,
                                               const float* __restrict__ gamma,
                                               const float* __restrict__ beta)
{
    __shared__ __align__(16) float As[4096];  // [slice(4)][am(8)][lane(32)][reg(4)]
    __shared__ __align__(16) float Bs[4096];  // [slice(4)][bn(16)][lane(32)][reg(2)]
    __shared__ float scS[DD], shS[DD];
    __shared__ float stS[2 * DD];
    const float* A = (MODE == 0) ? Ax : (MODE == 1 ? (const float*)g_h : (const float*)g_u);

    int tid = threadIdx.x;
    int row0 = blockIdx.x * 128;
    int col0 = blockIdx.y * 128;
    int lane = tid & 31, wid = tid >> 5;
    int warp_m = wid & 1;
    int warp_n = wid >> 1;

    if (MODE == 1 || MODE == 2) {
        if (tid < DD) bn_coeff(1, gamma, beta, tid, scS[tid], shS[tid]);
        if (MODE == 2 && tid < 2 * DD) stS[tid] = 0.f;
        __syncthreads();
    }

    float4 c[4][4];
#pragma unroll
    for (int i = 0; i < 4; i++)
#pragma unroll
        for (int j = 0; j < 4; j++) c[i][j] = make_float4(0.f, 0.f, 0.f, 0.f);

    int la_r = tid >> 3;
    int la_k = (tid & 7) * 4;
    int lbk = tid & 7;
    int lbc = (tid >> 3) * 4;

    for (int kt = 0; kt < K; kt += 32) {
        // ---- A tile -> permuted smem ----
#pragma unroll
        for (int i = 0; i < 4; i++) {
            int r = la_r + i * 32;
            int m = row0 + r;
            float4 v = make_float4(0.f, 0.f, 0.f, 0.f);
            if (m < NN) v = *(const float4*)(A + (size_t)m * K + kt + la_k);
            if (MODE == 1) {
                int k0 = kt + la_k;
                v.x = scS[k0 + 0] * v.x + shS[k0 + 0];
                v.y = scS[k0 + 1] * v.y + shS[k0 + 1];
                v.z = scS[k0 + 2] * v.z + shS[k0 + 2];
                v.w = scS[k0 + 3] * v.w + shS[k0 + 3];
            }
            int s  = la_k >> 3;
            int am = r >> 4, rr = r & 15;
            int base = ((s * 8 + am) * 32 + (rr & 7) * 4) * 4 + (rr >> 3) + ((la_k >> 2) & 1) * 2;
            As[base + 0]  = f2tf32(v.x);
            As[base + 4]  = f2tf32(v.y);
            As[base + 8]  = f2tf32(v.z);
            As[base + 12] = f2tf32(v.w);
        }
        // ---- B tile -> permuted smem ----
#pragma unroll
        for (int i = 0; i < 4; i++) {
            int k = lbk + i * 8;
            float4 v = *(const float4*)(B + (size_t)(kt + k) * NLD + col0 + lbc);
            int s  = k >> 3;
            int bn = lbc >> 3;
            int c7 = lbc & 7;
            int base = ((s * 16 + bn) * 32 + c7 * 4 + (k & 3)) * 2 + ((k >> 2) & 1);
            Bs[base + 0]  = f2tf32(v.x);
            Bs[base + 8]  = f2tf32(v.y);
            Bs[base + 16] = f2tf32(v.z);
            Bs[base + 24] = f2tf32(v.w);
        }
        __syncthreads();
#pragma unroll
        for (int s = 0; s < 4; s++) {
            uint4 a[4];
            uint2 bf[4];
#pragma unroll
            for (int i = 0; i < 4; i++)
                a[i] = *(const uint4*)&As[((s * 8 + warp_m * 4 + i) * 32 + lane) * 4];
#pragma unroll
            for (int j = 0; j < 4; j++)
                bf[j] = *(const uint2*)&Bs[((s * 16 + warp_n * 4 + j) * 32 + lane) * 2];
#pragma unroll
            for (int i = 0; i < 4; i++)
#pragma unroll
                for (int j = 0; j < 4; j++)
                    mma_tf32(c[i][j], a[i], bf[j]);
        }
        __syncthreads();
    }

    // ---- epilogue ----
    int g = lane >> 2, tk = lane & 3;
    float sreg[8], qreg[8];
    if (MODE == 2) {
#pragma unroll
        for (int j = 0; j < 8; j++) { sreg[j] = 0.f; qreg[j] = 0.f; }
    }
#pragma unroll
    for (int i = 0; i < 4; i++) {
        int rx = row0 + warp_m * 64 + i * 16 + g;
        int rz = rx + 8;
        if (MODE == 0) {
            float dx = (rx < NN) ? g_dinv[rx] : 0.f;
            float dz = (rz < NN) ? g_dinv[rz] : 0.f;
#pragma unroll
            for (int j = 0; j < 4; j++) {
                int cc = col0 + warp_n * 32 + j * 8 + tk * 2;
                if (rx < NN) {
                    __half2 v = __floats2half2_rn(c[i][j].x * dx, c[i][j].y * dx);
                    *(__half2*)&g_hh[(size_t)rx * DD + cc] = v;
                }
                if (rz < NN) {
                    __half2 v = __floats2half2_rn(c[i][j].z * dz, c[i][j].w * dz);
                    *(__half2*)&g_hh[(size_t)rz * DD + cc] = v;
                }
            }
        } else if (MODE == 1) {
#pragma unroll
            for (int j = 0; j < 4; j++) {
                int cc = col0 + warp_n * 32 + j * 8 + tk * 2;
                float2 bv = *(const float2*)(bias + cc);
                if (rx < NN) {
                    float2 v = make_float2(fmaxf(c[i][j].x + bv.x, 0.f), fmaxf(c[i][j].y + bv.y, 0.f));
                    *(float2*)&g_u[(size_t)rx * 256 + cc] = v;
                }
                if (rz < NN) {
                    float2 v = make_float2(fmaxf(c[i][j].z + bv.x, 0.f), fmaxf(c[i][j].w + bv.y, 0.f));
                    *(float2*)&g_u[(size_t)rz * 256 + cc] = v;
                }
            }
        } else {
#pragma unroll
            for (int j = 0; j < 4; j++) {
                int cc = col0 + warp_n * 32 + j * 8 + tk * 2;
                float2 bv = *(const float2*)(bias + cc);
                float a0 = scS[cc], a1 = scS[cc + 1];
                float d0 = shS[cc], d1 = shS[cc + 1];
                if (rx < NN) {
                    float2 r = *(const float2*)&g_h[(size_t)rx * DD + cc];
                    float2 v = make_float2(c[i][j].x + bv.x + a0 * r.x + d0,
                                           c[i][j].y + bv.y + a1 * r.y + d1);
                    *(float2*)&g_h[(size_t)rx * DD + cc] = v;
                    sreg[j * 2] += v.x;     qreg[j * 2] += v.x * v.x;
                    sreg[j * 2 + 1] += v.y; qreg[j * 2 + 1] += v.y * v.y;
                }
                if (rz < NN) {
                    float2 r = *(const float2*)&g_h[(size_t)rz * DD + cc];
                    float2 v = make_float2(c[i][j].z + bv.x + a0 * r.x + d0,
                                           c[i][j].w + bv.y + a1 * r.y + d1);
                    *(float2*)&g_h[(size_t)rz * DD + cc] = v;
                    sreg[j * 2] += v.x;     qreg[j * 2] += v.x * v.x;
                    sreg[j * 2 + 1] += v.y; qreg[j * 2 + 1] += v.y * v.y;
                }
            }
        }
    }
    if (MODE == 2) {
#pragma unroll
        for (int j = 0; j < 4; j++) {
            int cc = warp_n * 32 + j * 8 + tk * 2;   // col0 == 0 for MODE 2
            atomicAdd(&stS[cc],          sreg[j * 2]);
            atomicAdd(&stS[cc + 1],      sreg[j * 2 + 1]);
            atomicAdd(&stS[DD + cc],     qreg[j * 2]);
            atomicAdd(&stS[DD + cc + 1], qreg[j * 2 + 1]);
        }
        __syncthreads();
        if (tid < DD) {
            atomicAdd(&g_sum[2 * DD + tid], stS[tid]);
            atomicAdd(&g_sq[2 * DD + tid], stS[DD + tid]);
        }
    }
}

// ---------------- stats helper (block reduce + global atomic) ----------------
__device__ __forceinline__ void stats_reduce(int set, int lane,
                                             float s0, float s1, float s2, float s3,
                                             float q0, float q1, float q2, float q3) {
    __shared__ float ss[DD], sq[DD];
    if (threadIdx.x < DD) { ss[threadIdx.x] = 0.f; sq[threadIdx.x] = 0.f; }
    __syncthreads();
    int c = lane * 4;
    atomicAdd(&ss[c + 0], s0); atomicAdd(&ss[c + 1], s1);
    atomicAdd(&ss[c + 2], s2); atomicAdd(&ss[c + 3], s3);
    atomicAdd(&sq[c + 0], q0); atomicAdd(&sq[c + 1], q1);
    atomicAdd(&sq[c + 2], q2); atomicAdd(&sq[c + 3], q3);
    __syncthreads();
    if (threadIdx.x < DD) {
        atomicAdd(&g_sum[set * DD + threadIdx.x], ss[threadIdx.x]);
        atomicAdd(&g_sq[set * DD + threadIdx.x], sq[threadIdx.x]);
    }
}

// ---------------- CSR gather (fp16 rows): t[n] = (hs[n] + sum_s hs[s]) * dinv[n] + b ----
__global__ __launch_bounds__(256) void gather_kernel(const float* __restrict__ b) {
    int gw = (blockIdx.x * blockDim.x + threadIdx.x) >> 5;
    int lane = threadIdx.x & 31;
    int nw = (gridDim.x * blockDim.x) >> 5;
    float4 bb = *(const float4*)(b + lane * 4);
    const uint2* hv = (const uint2*)g_hh;   // 4 halves per uint2; 32 uint2 per row
    float s0 = 0, s1 = 0, s2 = 0, s3 = 0, q0 = 0, q1 = 0, q2 = 0, q3 = 0;
    for (int n = gw; n < NN; n += nw) {
        int st = g_off[n];
        int en = g_cursor[n];             // off[n] + cnt[n]
        uint2 rself = hv[(size_t)n * 32 + lane];
        float2 f0 = __half22float2(*(__half2*)&rself.x);
        float2 f1 = __half22float2(*(__half2*)&rself.y);
        float4 acc = make_float4(f0.x, f0.y, f1.x, f1.y);   // self loop (pre-scaled)
        int j = st;
        for (; j + 3 < en; j += 4) {
            int sA = g_srcs[j], sB = g_srcs[j + 1], sC = g_srcs[j + 2], sD = g_srcs[j + 3];
            uint2 rA = hv[(size_t)sA * 32 + lane];
            uint2 rB = hv[(size_t)sB * 32 + lane];
            uint2 rC = hv[(size_t)sC * 32 + lane];
            uint2 rD = hv[(size_t)sD * 32 + lane];
            float2 a0 = __half22float2(*(__half2*)&rA.x), a1 = __half22float2(*(__half2*)&rA.y);
            float2 b0 = __half22float2(*(__half2*)&rB.x), b1 = __half22float2(*(__half2*)&rB.y);
            float2 c0 = __half22float2(*(__half2*)&rC.x), c1 = __half22float2(*(__half2*)&rC.y);
            float2 d0 = __half22float2(*(__half2*)&rD.x), d1 = __half22float2(*(__half2*)&rD.y);
            acc.x += (a0.x + b0.x) + (c0.x + d0.x);
            acc.y += (a0.y + b0.y) + (c0.y + d0.y);
            acc.z += (a1.x + b1.x) + (c1.x + d1.x);
            acc.w += (a1.y + b1.y) + (c1.y + d1.y);
        }
        for (; j < en; j++) {
            int sA = g_srcs[j];
            uint2 rA = hv[(size_t)sA * 32 + lane];
            float2 a0 = __half22float2(*(__half2*)&rA.x), a1 = __half22float2(*(__half2*)&rA.y);
            acc.x += a0.x; acc.y += a0.y; acc.z += a1.x; acc.w += a1.y;
        }
        float dv = g_dinv[n];
        float4 t;
        t.x = acc.x * dv + bb.x; t.y = acc.y * dv + bb.y;
        t.z = acc.z * dv + bb.z; t.w = acc.w * dv + bb.w;
        *(float4*)&g_acc[(size_t)n * DD + lane * 4] = t;
        s0 += t.x; s1 += t.y; s2 += t.z; s3 += t.w;
        q0 += t.x * t.x; q1 += t.y * t.y; q2 += t.z * t.z; q3 += t.w * t.w;
    }
    stats_reduce(0, lane, s0, s1, s2, s3, q0, q1, q2, q3);
}

// ---------------- h2 = x + relu(bn1(t)) -> g_h, stats set 1 ----------------
__global__ __launch_bounds__(256) void passB_kernel(const float* __restrict__ x,
                                                    const float* __restrict__ gamma1,
                                                    const float* __restrict__ beta1) {
    int gt = blockIdx.x * blockDim.x + threadIdx.x;
    int gw = gt >> 5, lane = threadIdx.x & 31;
    int nw = (gridDim.x * blockDim.x) >> 5;
    int c = lane * 4;
    float sc0, sh0, sc1, sh1, sc2, sh2, sc3, sh3;
    bn_coeff(0, gamma1, beta1, c + 0, sc0, sh0);
    bn_coeff(0, gamma1, beta1, c + 1, sc1, sh1);
    bn_coeff(0, gamma1, beta1, c + 2, sc2, sh2);
    bn_coeff(0, gamma1, beta1, c + 3, sc3, sh3);
    float s0 = 0, s1 = 0, s2 = 0, s3 = 0, q0 = 0, q1 = 0, q2 = 0, q3 = 0;
    for (int r = gw; r < NN; r += nw) {
        size_t off = (size_t)r * DD + c;
        float4 t  = *(const float4*)&g_acc[off];
        float4 xv = *(const float4*)(x + off);
        float4 v;
        v.x = xv.x + fmaxf(sc0 * t.x + sh0, 0.f);
        v.y = xv.y + fmaxf(sc1 * t.y + sh1, 0.f);
        v.z = xv.z + fmaxf(sc2 * t.z + sh2, 0.f);
        v.w = xv.w + fmaxf(sc3 * t.w + sh3, 0.f);
        *(float4*)&g_h[off] = v;
        s0 += v.x; s1 += v.y; s2 += v.z; s3 += v.w;
        q0 += v.x * v.x; q1 += v.y * v.y; q2 += v.z * v.z; q3 += v.w * v.w;
    }
    stats_reduce(1, lane, s0, s1, s2, s3, q0, q1, q2, q3);
}

// ---------------- out = bn3(h3) ----------------
__global__ __launch_bounds__(256) void final_kernel(float* __restrict__ out,
                                                    const float* __restrict__ gamma3,
                                                    const float* __restrict__ beta3) {
    int c = (threadIdx.x & 31) * 4;
    float sc0, sh0, sc1, sh1, sc2, sh2, sc3, sh3;
    bn_coeff(2, gamma3, beta3, c + 0, sc0, sh0);
    bn_coeff(2, gamma3, beta3, c + 1, sc1, sh1);
    bn_coeff(2, gamma3, beta3, c + 2, sc2, sh2);
    bn_coeff(2, gamma3, beta3, c + 3, sc3, sh3);
    int total = NN * (DD / 4);
    for (int f = blockIdx.x * blockDim.x + threadIdx.x; f < total; f += gridDim.x * blockDim.x) {
        float4 h = ((const float4*)g_h)[f];
        float4 v;
        v.x = sc0 * h.x + sh0;
        v.y = sc1 * h.y + sh1;
        v.z = sc2 * h.z + sh2;
        v.w = sc3 * h.w + sh3;
        ((float4*)out)[f] = v;
    }
}

// ---------------- host (single stream, fully serial) ----------------
extern "C" void kernel_launch(void* const* d_in, const int* in_sizes, int n_in,
                              void* d_out, int out_size) {
    const float* x      = (const float*)d_in[0];
    const int*   ei     = (const int*)  d_in[1];
    const float* W      = (const float*)d_in[2];
    const float* b      = (const float*)d_in[3];
    const float* gamma1 = (const float*)d_in[4];
    const float* beta1  = (const float*)d_in[5];
    const float* gamma2 = (const float*)d_in[6];
    const float* beta2  = (const float*)d_in[7];
    const float* gamma3 = (const float*)d_in[8];
    const float* beta3  = (const float*)d_in[9];
    const float* W1     = (const float*)d_in[10];
    const float* b1     = (const float*)d_in[11];
    const float* W2     = (const float*)d_in[12];
    const float* b2     = (const float*)d_in[13];
    float* out = (float*)d_out;
    int E = in_sizes[1] / 2;

    init_kernel<<<(NN + 255) / 256, 256>>>();
    count_kernel<<<(E + 255) / 256, 256>>>(ei, E);
    scan1_kernel<<<NBLK_SCAN, 256>>>();
    scan3_kernel<<<(NN + 255) / 256, 256>>>();
    fill_kernel<<<(E + 255) / 256, 256>>>(ei, E);

    gemm_tc<0, 128, 128><<<dim3((NN + 127) / 128, 1), 256>>>(x, W, nullptr, nullptr, nullptr);
    gather_kernel<<<2048, 256>>>(b);
    passB_kernel<<<1024, 256>>>(x, gamma1, beta1);
    gemm_tc<1, 128, 256><<<dim3((NN + 127) / 128, 2), 256>>>(nullptr, W1, b1, gamma2, beta2);
    gemm_tc<2, 256, 128><<<dim3((NN + 127) / 128, 1), 256>>>(nullptr, W2, b2, gamma2, beta2);
    final_kernel<<<2048, 256>>>(out, gamma3, beta3);
}